// round 17
// baseline (speedup 1.0000x reference)
#include <cuda_runtime.h>
#include <cuda_bf16.h>
#include <cuda_fp16.h>
#include <math.h>
#include <stdint.h>

#define B_   2
#define C_   128
#define N_   4096
#define K_   16
#define DIM_ 256
#define PH_  64
#define AH_  1024
#define M_   (N_ * K_)          // 65536 columns per batch in (n,k) space

// ---------------- scratch ---------------------------------------------------
__device__ float g_x    [(size_t)B_ * 2 * C_ * N_];
__device__ float g_t    [(size_t)B_ * C_ * N_];
__device__ float g_value[(size_t)B_ * C_ * N_];
__device__ float g_vf   [(size_t)B_ * DIM_ * N_];
__device__ float g_u    [(size_t)B_ * AH_ * N_];
__device__ __half g_vt  [(size_t)B_ * N_ * AH_];       // v transposed (fp16)
__device__ int   g_idx  [(size_t)B_ * N_ * K_];
__device__ __half g_h   [(size_t)B_ * AH_ * M_];       // h (fp16, c-major)
__device__ float g_agg  [(size_t)B_ * DIM_ * N_];
__device__ float g_part [(size_t)B_ * 512 * AH_ * 2];
__device__ float g_partp[(size_t)512 * 9];
__device__ float g_Wuq  [AH_ * C_];
__device__ float g_Wvk  [AH_ * C_];
__device__ float g_bias1[AH_];
__device__ float g_wsc  [PH_ * 3];                     // pos BN folded: w*g/sigma
__device__ float g_sh2  [PH_];                         // pos BN folded shift
__device__ float g_sca  [AH_];
__device__ float g_sha  [AH_];
// fp16 image of att_w2: 16 K-chunks x 32KB = 512KB
__device__ unsigned int g_w2img[16 * 32768 / 4];
// fp16 image of Wmid = concat(att_w1@pos_w2, pos_w2): 10 chunks x 16KB
__device__ unsigned int g_wmidimg[10 * 16384 / 4];
// fp16 images of Wuq/Wvk: 8 c-chunks x 32KB (2 kc x 16KB)
__device__ unsigned int g_wuqimg[8 * 32768 / 4];
__device__ unsigned int g_wvkimg[8 * 32768 / 4];

// ---------------- helpers ---------------------------------------------------
__device__ __forceinline__ uint32_t smem_u32(const void* p) {
    uint32_t a;
    asm("{ .reg .u64 t; cvta.to.shared.u64 t, %1; cvt.u32.u64 %0, t; }" : "=r"(a) : "l"(p));
    return a;
}
#define SWZ128(b) ((b) ^ (((b) >> 3) & 0x70))
__device__ __forceinline__ uint32_t pack_h2(float a, float b) {
    __half2 t = __floats2half2_rn(a, b);
    return *reinterpret_cast<uint32_t*>(&t);
}
__device__ __forceinline__ void ldm_x4(uint32_t* r, uint32_t addr) {
    asm volatile("ldmatrix.sync.aligned.m8n8.x4.shared.b16 {%0,%1,%2,%3}, [%4];"
        : "=r"(r[0]), "=r"(r[1]), "=r"(r[2]), "=r"(r[3]) : "r"(addr));
}
__device__ __forceinline__ void mma16816h(float* d, const uint32_t* a, const uint32_t* b) {
    asm volatile(
        "mma.sync.aligned.m16n8k16.row.col.f32.f16.f16.f32 "
        "{%0,%1,%2,%3}, {%4,%5,%6,%7}, {%8,%9}, {%0,%1,%2,%3};"
        : "+f"(d[0]), "+f"(d[1]), "+f"(d[2]), "+f"(d[3])
        : "r"(a[0]), "r"(a[1]), "r"(a[2]), "r"(a[3]), "r"(b[0]), "r"(b[1]));
}
__device__ __forceinline__ void cp_async16(uint32_t dst, const void* src) {
    asm volatile("cp.async.cg.shared.global [%0], [%1], 16;" :: "r"(dst), "l"(src));
}
#define CP_COMMIT() asm volatile("cp.async.commit_group;" ::: "memory")
#define CP_WAIT0()  asm volatile("cp.async.wait_group 0;" ::: "memory")

// ---------------- concat ----------------------------------------------------
__global__ void concat_kernel(const float* __restrict__ key,
                              const float* __restrict__ query,
                              float* __restrict__ x) {
    size_t i = (size_t)blockIdx.x * blockDim.x + threadIdx.x;
    if (i >= (size_t)B_ * 2 * C_ * N_) return;
    int n = (int)(i % N_);
    int c = (int)((i / N_) % (2 * C_));
    int b = (int)(i / ((size_t)N_ * 2 * C_));
    float v;
    if (c < C_) v = key  [((size_t)b * C_ + c) * N_ + n];
    else        v = query[((size_t)b * C_ + (c - C_)) * N_ + n];
    x[i] = v;
}

// ---------------- KNN -------------------------------------------------------
__global__ void knn_kernel(const float* __restrict__ pos, int* __restrict__ idx) {
    const int b = blockIdx.y;
    const int n = blockIdx.x * blockDim.x + threadIdx.x;
    const float* p = pos + (size_t)b * 3 * N_;
    const float qx = p[n], qy = p[N_ + n], qz = p[2 * N_ + n];
    const float qs = qx * qx + qy * qy + qz * qz;
    float bd[K_]; int bi[K_];
#pragma unroll
    for (int j = 0; j < K_; j++) { bd[j] = 3.4e38f; bi[j] = 0; }
    __shared__ float sx[512], sy[512], sz[512], ss[512];
    for (int t0 = 0; t0 < N_; t0 += 512) {
        __syncthreads();
        for (int i = threadIdx.x; i < 512; i += blockDim.x) {
            float x = p[t0 + i], y = p[N_ + t0 + i], z = p[2 * N_ + t0 + i];
            sx[i] = x; sy[i] = y; sz[i] = z; ss[i] = x * x + y * y + z * z;
        }
        __syncthreads();
        for (int i = 0; i < 512; i++) {
            float d = qs + ss[i] - 2.0f * (qx * sx[i] + qy * sy[i] + qz * sz[i]);
            if (d < bd[K_ - 1]) {
                int j = K_ - 1;
                while (j > 0 && d < bd[j - 1]) { bd[j] = bd[j - 1]; bi[j] = bi[j - 1]; j--; }
                bd[j] = d; bi[j] = t0 + i;
            }
        }
    }
    int* op = idx + ((size_t)b * N_ + n) * K_;
#pragma unroll
    for (int j = 0; j < K_; j++) op[j] = bi[j];
}

// ---------------- precompute small products ---------------------------------
__global__ void smallmm_kernel(const float* __restrict__ A, const float* __restrict__ Bm,
                               float* __restrict__ Cc, int O, int Id, int J, int tr) {
    int t = blockIdx.x * 256 + threadIdx.x;
    if (t >= O * J) return;
    int o = t / J, j = t % J;
    float s = 0.0f;
    for (int d = 0; d < Id; d++) s += A[o * Id + d] * Bm[d * J + j];
    if (tr) Cc[j * O + o] = s; else Cc[o * J + j] = s;
}
__global__ void bias1_kernel(const float* __restrict__ w1, const float* __restrict__ bq,
                             const float* __restrict__ bk, const float* __restrict__ pb2,
                             const float* __restrict__ ab1, float* __restrict__ out) {
    int o = blockIdx.x * 256 + threadIdx.x;
    if (o >= AH_) return;
    float s = ab1[o];
    for (int d = 0; d < DIM_; d++) s += w1[o * DIM_ + d] * (bq[d] - bk[d] + pb2[d]);
    out[o] = s;
}

// ---------------- pos_rel moment stats ---------------------------------------
__global__ void posstat_kernel(const float* __restrict__ pos, const int* __restrict__ idx,
                               float* __restrict__ partp) {
    int s = blockIdx.x * 256 + threadIdx.x;        // 131072 samples
    int k = s & 15, n = (s >> 4) & (N_ - 1), b = s >> 16;
    int mi = idx[((size_t)b * N_ + n) * K_ + k];
    const float* p = pos + (size_t)b * 3 * N_;
    float rx = p[n] - p[mi], ry = p[N_ + n] - p[N_ + mi], rz = p[2 * N_ + n] - p[2 * N_ + mi];
    float v[9] = {rx, ry, rz, rx * rx, ry * ry, rz * rz, rx * ry, rx * rz, ry * rz};
    __shared__ float red[8][9];
#pragma unroll
    for (int i = 0; i < 9; i++) {
        float x = v[i];
#pragma unroll
        for (int o = 16; o; o >>= 1) x += __shfl_xor_sync(0xffffffffu, x, o);
        if ((threadIdx.x & 31) == 0) red[threadIdx.x >> 5][i] = x;
    }
    __syncthreads();
    if (threadIdx.x < 9) {
        float sum = 0.f;
#pragma unroll
        for (int w = 0; w < 8; w++) sum += red[w][threadIdx.x];
        partp[blockIdx.x * 9 + threadIdx.x] = sum;
    }
}

// ---------------- pos BN analytic finalize -> folded wsc/sh2 -----------------
__global__ void posbn_finalize(const float* __restrict__ partp,
                               const float* __restrict__ w, const float* __restrict__ bias,
                               const float* __restrict__ g, const float* __restrict__ be,
                               float* __restrict__ wsc, float* __restrict__ sh2) {
    __shared__ double sums[9];
    int t = threadIdx.x;
    if (t < 9) {
        double s = 0.0;
        for (int i = 0; i < 512; i++) s += (double)partp[i * 9 + t];
        sums[t] = s;
    }
    __syncthreads();
    if (t < PH_) {
        double cnt = (double)B_ * M_;
        double S0 = sums[0], S1 = sums[1], S2 = sums[2];
        double Qxx = sums[3], Qyy = sums[4], Qzz = sums[5];
        double Qxy = sums[6], Qxz = sums[7], Qyz = sums[8];
        double w0 = w[t * 3], w1 = w[t * 3 + 1], w2 = w[t * 3 + 2];
        double dotm = (w0 * S0 + w1 * S1 + w2 * S2) / cnt;
        double mean = dotm + bias[t];
        double qf = w0 * w0 * Qxx + w1 * w1 * Qyy + w2 * w2 * Qzz
                  + 2.0 * (w0 * w1 * Qxy + w0 * w2 * Qxz + w1 * w2 * Qyz);
        double var = qf / cnt - dotm * dotm;
        double sc = (double)g[t] / sqrt(var + 1e-5);
        wsc[t * 3]     = (float)(w0 * sc);
        wsc[t * 3 + 1] = (float)(w1 * sc);
        wsc[t * 3 + 2] = (float)(w2 * sc);
        sh2[t] = (float)((bias[t] - mean) * sc + be[t]);
    }
}

// ---------------- att_w2 -> pre-swizzled fp16 image --------------------------
__global__ void prep_w2_kernel(const float* __restrict__ w2, unsigned int* __restrict__ img) {
    int t = blockIdx.x * 256 + threadIdx.x;
    if (t >= 256 * 256) return;
    int c = t >> 8, k4 = t & 255;
    int k = k4 * 4;
    int q = k >> 6, kl = k & 63;
    const float* src = w2 + (size_t)c * AH_ + k;
    uint32_t off = SWZ128((uint32_t)((c >> 3) * 1024 + (c & 7) * 128 + kl * 2));
    char* base = (char*)img + (size_t)q * 32768;
    *(uint2*)(base + off) = make_uint2(pack_h2(src[0], src[1]), pack_h2(src[2], src[3]));
}

// ---------------- Wmid -> pre-swizzled fp16 image ----------------------------
__global__ void prep_wmid_kernel(const float* __restrict__ att_w1,
                                 const float* __restrict__ pos_w2,
                                 unsigned int* __restrict__ img) {
    int t = blockIdx.x * 256 + threadIdx.x;
    if (t >= 1280 * 16) return;
    int c = t >> 4, k4 = t & 15;
    float f[4];
    if (c < AH_) {
#pragma unroll 4
        for (int kk = 0; kk < 4; kk++) {
            float s = 0.0f;
            for (int d = 0; d < DIM_; d++)
                s += att_w1[(size_t)c * DIM_ + d] * pos_w2[d * PH_ + k4 * 4 + kk];
            f[kk] = s;
        }
    } else {
#pragma unroll
        for (int kk = 0; kk < 4; kk++) f[kk] = pos_w2[(c - AH_) * PH_ + k4 * 4 + kk];
    }
    int ct = c >> 7, cl = c & 127;
    uint32_t off = (uint32_t)((cl >> 3) * 1024 + (cl & 7) * 128 +
                              ((k4 * 8) ^ ((cl & 7) << 4)));
    char* base = (char*)img + (size_t)ct * 16384;
    *(uint2*)(base + off) = make_uint2(pack_h2(f[0], f[1]), pack_h2(f[2], f[3]));
}

// ---------------- Wuq/Wvk [AH][C=128] -> fp16 image: 8 c-chunks x 32KB --------
__global__ void prep_wuv_kernel(const float* __restrict__ W, unsigned int* __restrict__ img) {
    int t = blockIdx.x * 256 + threadIdx.x;
    if (t >= AH_ * 32) return;
    int c = t >> 5, k4 = t & 31;
    int k = k4 * 4;
    int kc = k >> 6, kl = k & 63;
    const float* src = W + (size_t)c * C_ + k;
    int ct = c >> 7, cl = c & 127;
    uint32_t off = (uint32_t)((cl >> 3) * 1024 + (cl & 7) * 128 +
                              ((kl * 2) ^ ((cl & 7) << 4)));
    char* base = (char*)img + (size_t)ct * 32768 + (size_t)kc * 16384;
    *(uint2*)(base + off) = make_uint2(pack_h2(src[0], src[1]), pack_h2(src[2], src[3]));
}

// ---------------- generic fp32 SGEMM (small GEMMs) --------------------------
template <int FLAGS>
__global__ void sgemm_kernel(const float* __restrict__ W, const float* __restrict__ Xg,
                             const float* __restrict__ bias, float* __restrict__ outg,
                             const float* __restrict__ resg, int O, int I, int M) {
    const int b = blockIdx.z;
    const float* X = Xg + (size_t)b * I * M;
    float* out = outg + (size_t)b * O * M;
    const float* res = (FLAGS & 4) ? (resg + (size_t)b * O * M) : nullptr;
    __shared__ float Ws[8][132];
    __shared__ float Xs[8][128];
    const int tid = threadIdx.x;
    const int tx = tid & 15, ty = tid >> 4;
    const int o0 = blockIdx.y * 128, m0 = blockIdx.x * 128;
    const int wr = tid >> 1, wc = (tid & 1) * 4;
    const int xr = tid >> 5, xc = (tid & 31) * 4;
    float acc[8][8];
#pragma unroll
    for (int i = 0; i < 8; i++)
#pragma unroll
        for (int j = 0; j < 8; j++) acc[i][j] = 0.0f;
    for (int kt = 0; kt < I; kt += 8) {
        float4 wv = *(const float4*)&W[(size_t)(o0 + wr) * I + kt + wc];
        float4 xv = *(const float4*)&X[(size_t)(kt + xr) * M + m0 + xc];
        __syncthreads();
        Ws[wc + 0][wr] = wv.x; Ws[wc + 1][wr] = wv.y;
        Ws[wc + 2][wr] = wv.z; Ws[wc + 3][wr] = wv.w;
        *(float4*)&Xs[xr][xc] = xv;
        __syncthreads();
#pragma unroll
        for (int k = 0; k < 8; k++) {
            float a[8], bb[8];
            *(float4*)&a[0]  = *(const float4*)&Ws[k][ty * 8];
            *(float4*)&a[4]  = *(const float4*)&Ws[k][ty * 8 + 4];
            *(float4*)&bb[0] = *(const float4*)&Xs[k][tx * 8];
            *(float4*)&bb[4] = *(const float4*)&Xs[k][tx * 8 + 4];
#pragma unroll
            for (int i = 0; i < 8; i++)
#pragma unroll
                for (int j = 0; j < 8; j++) acc[i][j] += a[i] * bb[j];
        }
    }
#pragma unroll
    for (int i = 0; i < 8; i++) {
        const int o = o0 + ty * 8 + i;
        const float bv = bias[o];
        float* orow = out + (size_t)o * M + m0 + tx * 8;
        const float* rrow = (FLAGS & 4) ? (res + (size_t)o * M + m0 + tx * 8) : nullptr;
#pragma unroll
        for (int jj = 0; jj < 8; jj += 4) {
            float4 v;
            v.x = acc[i][jj + 0] + bv; v.y = acc[i][jj + 1] + bv;
            v.z = acc[i][jj + 2] + bv; v.w = acc[i][jj + 3] + bv;
            if (FLAGS & 1) { v.x = fmaxf(v.x, 0.f); v.y = fmaxf(v.y, 0.f);
                             v.z = fmaxf(v.z, 0.f); v.w = fmaxf(v.w, 0.f); }
            if (FLAGS & 2) { float4 old = *(float4*)&orow[jj];
                             v.x += old.x; v.y += old.y; v.z += old.z; v.w += old.w; }
            if (FLAGS & 4) { float4 r = *(const float4*)&rrow[jj];
                             v.x += r.x; v.y += r.y; v.z += r.z; v.w += r.w; }
            *(float4*)&orow[jj] = v;
        }
    }
}

// ---------------- BN finalize (attn h stats) ----------------------------------
__global__ void finalize_stats(const float* __restrict__ part, int P, int ps, int cs,
                               const float* __restrict__ g, const float* __restrict__ be,
                               float* __restrict__ sc, float* __restrict__ sh, float cnt) {
    int c = blockIdx.x;
    double s = 0.0, q = 0.0;
    for (int p = threadIdx.x; p < P; p += blockDim.x) {
        size_t o = ((size_t)p * ps + (size_t)c * cs) * 2;
        s += (double)part[o]; q += (double)part[o + 1];
    }
    __shared__ double S[256], Q[256];
    S[threadIdx.x] = s; Q[threadIdx.x] = q;
    __syncthreads();
    for (int st = 128; st > 0; st >>= 1) {
        if ((int)threadIdx.x < st) {
            S[threadIdx.x] += S[threadIdx.x + st];
            Q[threadIdx.x] += Q[threadIdx.x + st];
        }
        __syncthreads();
    }
    if (threadIdx.x == 0) {
        double mean = S[0] / (double)cnt;
        double var  = Q[0] / (double)cnt - mean * mean;
        float scv = g[c] * (float)(1.0 / sqrt(var + 1e-5));
        sc[c] = scv;
        sh[c] = be[c] - (float)mean * scv;
    }
}

// ---------------- u/v GEMM on fp16 HMMA (single W buf, 2 blocks/SM) ----------
#define UV_X     0
#define UV_W     32768
#define UV_TR    65536
#define UV_SMEM  100352

__global__ __launch_bounds__(256, 2) void uv_hmma(
    const float* __restrict__ query, const float* __restrict__ key,
    const unsigned int* __restrict__ wuqimg, const unsigned int* __restrict__ wvkimg,
    float* __restrict__ ug, __half* __restrict__ vt) {
    extern __shared__ char smc[];
    const uint32_t sb = smem_u32(smc);
    const int tid = threadIdx.x, lane = tid & 31, wid = tid >> 5;
    const int z = blockIdx.y;
    const int b = z & 1, which = z >> 1;
    const int n0 = blockIdx.x * 128;
    const float* X = (which == 0 ? query : key) + (size_t)b * C_ * N_;
    const unsigned int* wimg = (which == 0 ? wuqimg : wvkimg);
    float* uout = ug + (size_t)b * AH_ * N_;
    const int warp_cg = wid >> 1;
    const int warp_mg = wid & 1;

    {
        const uint4* src = (const uint4*)wimg;
        uint32_t dst = sb + UV_W;
#pragma unroll
        for (int it = 0; it < 8; it++)
            cp_async16(dst + (it * 256 + tid) * 16, src + it * 256 + tid);
        CP_COMMIT();
    }
    {
        char* xbase = smc + UV_X;
        int m = tid & 127, khalf = tid >> 7;
#pragma unroll
        for (int k2 = 0; k2 < 32; k2++) {
            int k = khalf * 64 + k2 * 2;
            int kl = k & 63;
            float x0 = X[(size_t)k * N_ + n0 + m];
            float x1 = X[(size_t)(k + 1) * N_ + n0 + m];
            uint32_t off = (uint32_t)((m >> 3) * 1024 + (m & 7) * 128 +
                                      ((kl * 2) ^ ((m & 7) << 4)));
            char* dst = xbase + khalf * 16384;
            *(uint32_t*)(dst + off) = pack_h2(x0, x1);
        }
    }
    CP_WAIT0();
    __syncthreads();

    const int g = lane >> 3, lr = lane & 7;
    const int wrow = warp_cg * 32 + (g & 1) * 8 + lr;
    const int xrow = warp_mg * 64 + (g >> 1) * 8 + lr;
    const int wkb0 = (g >> 1) * 16;
    const int xkb0 = (g & 1) * 16;
    const uint32_t sX = sb + UV_X;
    const uint32_t sW = sb + UV_W;

    for (int ct = 0; ct < 8; ct++) {
        float acc[2][8][4];
#pragma unroll
        for (int a = 0; a < 2; a++)
#pragma unroll
            for (int q = 0; q < 8; q++)
#pragma unroll
                for (int j = 0; j < 4; j++) acc[a][q][j] = 0.0f;
#pragma unroll
        for (int kc = 0; kc < 2; kc++) {
#pragma unroll
            for (int ks = 0; ks < 4; ks++) {
                uint32_t Wf[2][4], Xf[4][4];
#pragma unroll
                for (int ct2 = 0; ct2 < 2; ct2++) {
                    int cr = wrow + ct2 * 16;
                    uint32_t ro = (uint32_t)((cr >> 3) * 1024 + (cr & 7) * 128);
                    uint32_t kb = (uint32_t)((ks * 32 + wkb0) ^ ((cr & 7) << 4));
                    ldm_x4(Wf[ct2], sW + kc * 16384 + ro + kb);
                }
#pragma unroll
                for (int np = 0; np < 4; np++) {
                    int mr = xrow + np * 16;
                    uint32_t ro = (uint32_t)((mr >> 3) * 1024 + (mr & 7) * 128);
                    uint32_t kb = (uint32_t)((ks * 32 + xkb0) ^ ((mr & 7) << 4));
                    ldm_x4(Xf[np], sX + kc * 16384 + ro + kb);
                }
#pragma unroll
                for (int ct2 = 0; ct2 < 2; ct2++)
#pragma unroll
                    for (int np = 0; np < 4; np++) {
                        mma16816h(acc[ct2][np * 2],     Wf[ct2], &Xf[np][0]);
                        mma16816h(acc[ct2][np * 2 + 1], Wf[ct2], &Xf[np][2]);
                    }
            }
        }
        if (which == 0) {
#pragma unroll
            for (int ct2 = 0; ct2 < 2; ct2++) {
#pragma unroll
                for (int j = 0; j < 4; j++) {
                    int c_g = ct * 128 + warp_cg * 32 + ct2 * 16 + (lane >> 2) + (j >> 1) * 8;
                    float* orow = uout + (size_t)c_g * N_ + n0;
#pragma unroll
                    for (int q = 0; q < 8; q++) {
                        int m_loc = warp_mg * 64 + q * 8 + (lane & 3) * 2 + (j & 1);
                        orow[m_loc] = acc[ct2][q][j];
                    }
                }
            }
        } else {
            __half* trs = (__half*)(smc + UV_TR);
#pragma unroll
            for (int ct2 = 0; ct2 < 2; ct2++)
#pragma unroll
                for (int j = 0; j < 4; j++) {
                    int c_loc = warp_cg * 32 + ct2 * 16 + (lane >> 2) + (j >> 1) * 8;
#pragma unroll
                    for (int q = 0; q < 8; q++) {
                        int m_loc = warp_mg * 64 + q * 8 + (lane & 3) * 2 + (j & 1);
                        trs[m_loc * 136 + c_loc] = __float2half(acc[ct2][q][j]);
                    }
                }
            __syncthreads();
            __half* dvt = vt + ((size_t)b * N_ + n0) * AH_ + ct * 128;
#pragma unroll
            for (int it = 0; it < 8; it++) {
                int e = it * 256 + tid;
                int row = e >> 4, col = e & 15;
                *(uint4*)(dvt + (size_t)row * AH_ + col * 8) =
                    *(uint4*)&trs[row * 136 + col * 8];
            }
        }
        if (ct + 1 < 8) {
            __syncthreads();
            const uint4* src = (const uint4*)wimg + (ct + 1) * 2048;
            uint32_t dst = sb + UV_W;
#pragma unroll
            for (int it = 0; it < 8; it++)
                cp_async16(dst + (it * 256 + tid) * 16, src + it * 256 + tid);
            CP_COMMIT();
            CP_WAIT0();
            __syncthreads();
        }
    }
}

// ---------------- fused mid on fp16 HMMA (h only; t1 computed on the fly) ----
#define FM_X     0
#define FM_W(s)  (16384 + (s) * 16384)
#define FM_VG    49152
#define FM_U     82944
#define FM_RED   87552
#define FM_SIDX  89600
#define FM_SMEM  90112

__global__ __launch_bounds__(256, 2) void fused_mid_hmma(
    const float* __restrict__ pos, const int* __restrict__ idx,
    const float* __restrict__ wsc, const float* __restrict__ sh2,
    const unsigned int* __restrict__ wimg,
    const float* __restrict__ bias1, const float* __restrict__ u,
    const __half* __restrict__ vt,
    __half* __restrict__ h, float* __restrict__ part) {
    extern __shared__ char smc[];
    const uint32_t sb = smem_u32(smc);
    const int tid = threadIdx.x, lane = tid & 31, wid = tid >> 5;
    const int b = blockIdx.y, m0 = blockIdx.x * 128;
    const int warp_cg = wid >> 1;
    const int warp_mg = wid & 1;

    int* sidx = (int*)(smc + FM_SIDX);
    __half* vgsh = (__half*)(smc + FM_VG);
    float* us  = (float*)(smc + FM_U);
    float* redS = (float*)(smc + FM_RED);
    float* redQ = redS + 256;

    if (tid < 128) sidx[tid] = idx[((size_t)b * N_ + (m0 >> 4)) * K_ + tid];

    {
        const uint4* src = (const uint4*)wimg;
        uint32_t dst = sb + FM_W(0);
#pragma unroll
        for (int it = 0; it < 4; it++)
            cp_async16(dst + (it * 256 + tid) * 16, src + it * 256 + tid);
        CP_COMMIT();
    }
    __syncthreads();   // sidx visible for X-compute
    {
        const float* pp = pos + (size_t)b * 3 * N_;
        char* xd = smc + FM_X;
        int m = tid & 127, khalf = tid >> 7;
        int n = (m0 + m) >> 4;
        int mi = sidx[m];
        float rx = pp[n] - pp[mi];
        float ry = pp[N_ + n] - pp[N_ + mi];
        float rz = pp[2 * N_ + n] - pp[2 * N_ + mi];
#pragma unroll
        for (int k2 = 0; k2 < 16; k2++) {
            int k = khalf * 32 + k2 * 2;
            float x0 = fmaxf(wsc[3 * k] * rx + wsc[3 * k + 1] * ry + wsc[3 * k + 2] * rz + sh2[k], 0.f);
            float x1 = fmaxf(wsc[3 * k + 3] * rx + wsc[3 * k + 4] * ry + wsc[3 * k + 5] * rz + sh2[k + 1], 0.f);
            uint32_t off = (uint32_t)((m >> 3) * 1024 + (m & 7) * 128 +
                                      ((k * 2) ^ ((m & 7) << 4)));
            *(uint32_t*)(xd + off) = pack_h2(x0, x1);
        }
    }
    CP_WAIT0();
    __syncthreads();

    const int g = lane >> 3, lr = lane & 7;
    const int wrow = warp_cg * 32 + (g & 1) * 8 + lr;
    const int xrow = warp_mg * 64 + (g >> 1) * 8 + lr;
    const int wkb0 = (g >> 1) * 16;
    const int xkb0 = (g & 1) * 16;
    const uint32_t sX = sb + FM_X;
    const __half* vtb = vt + (size_t)b * N_ * AH_;
    const int n0 = m0 >> 4;

    for (int ct = 0; ct < 8; ct++) {
        const int s = ct & 1;
        if (ct + 1 < 8) {
            const uint4* src = (const uint4*)wimg + (ct + 1) * 1024;
            uint32_t dst = sb + FM_W(s ^ 1);
#pragma unroll
            for (int it = 0; it < 4; it++)
                cp_async16(dst + (it * 256 + tid) * 16, src + it * 256 + tid);
            CP_COMMIT();
        }
        {
#pragma unroll
            for (int jj = 0; jj < 16; jj++) {
                int j = wid * 16 + jj;
                const __half* row = vtb + (size_t)sidx[j] * AH_ + ct * 128;
#pragma unroll
                for (int cc = 0; cc < 2; cc++) {
                    int c = cc * 64 + lane * 2;
                    __half2 hv = *(const __half2*)(row + c);
                    vgsh[c * 132 + j] = hv.x;
                    vgsh[(c + 1) * 132 + j] = hv.y;
                }
            }
#pragma unroll
            for (int it = 0; it < 4; it++) {
                int e = it * 256 + tid;
                int c = e >> 3, nn = e & 7;
                us[c * 9 + nn] = u[((size_t)b * AH_ + ct * 128 + c) * N_ + n0 + nn]
                               + bias1[ct * 128 + c];
            }
        }
        const uint32_t sW = sb + FM_W(s);
        float acc[2][8][4];
#pragma unroll
        for (int a = 0; a < 2; a++)
#pragma unroll
            for (int q = 0; q < 8; q++)
#pragma unroll
                for (int j = 0; j < 4; j++) acc[a][q][j] = 0.0f;
#pragma unroll
        for (int ks = 0; ks < 4; ks++) {
            uint32_t Wf[2][4], Xf[4][4];
#pragma unroll
            for (int ct2 = 0; ct2 < 2; ct2++) {
                int cr = wrow + ct2 * 16;
                uint32_t ro = (uint32_t)((cr >> 3) * 1024 + (cr & 7) * 128);
                uint32_t kb = (uint32_t)((ks * 32 + wkb0) ^ ((cr & 7) << 4));
                ldm_x4(Wf[ct2], sW + ro + kb);
            }
#pragma unroll
            for (int np = 0; np < 4; np++) {
                int mr = xrow + np * 16;
                uint32_t ro = (uint32_t)((mr >> 3) * 1024 + (mr & 7) * 128);
                uint32_t kb = (uint32_t)((ks * 32 + xkb0) ^ ((mr & 7) << 4));
                ldm_x4(Xf[np], sX + ro + kb);
            }
#pragma unroll
            for (int ct2 = 0; ct2 < 2; ct2++)
#pragma unroll
                for (int np = 0; np < 4; np++) {
                    mma16816h(acc[ct2][np * 2],     Wf[ct2], &Xf[np][0]);
                    mma16816h(acc[ct2][np * 2 + 1], Wf[ct2], &Xf[np][2]);
                }
        }
        __syncthreads();
        {
            float sS[2][2], sQ[2][2];
#pragma unroll
            for (int a = 0; a < 2; a++) { sS[a][0] = sS[a][1] = 0.f; sQ[a][0] = sQ[a][1] = 0.f; }
#pragma unroll
            for (int ct2 = 0; ct2 < 2; ct2++) {
#pragma unroll
                for (int rh = 0; rh < 2; rh++) {
                    int c_loc = warp_cg * 32 + ct2 * 16 + (lane >> 2) + rh * 8;
                    int c_g = ct * 128 + c_loc;
                    __half* hrow = h + ((size_t)b * AH_ + c_g) * M_ + m0;
#pragma unroll
                    for (int q = 0; q < 8; q++) {
                        int m_loc = warp_mg * 64 + q * 8 + (lane & 3) * 2;
                        float base = us[c_loc * 9 + (m_loc >> 4)];
                        float v0 = acc[ct2][q][rh * 2]     + base
                                 - __half2float(vgsh[c_loc * 132 + m_loc]);
                        float v1 = acc[ct2][q][rh * 2 + 1] + base
                                 - __half2float(vgsh[c_loc * 132 + m_loc + 1]);
                        *(__half2*)(hrow + m_loc) = __floats2half2_rn(v0, v1);
                        sS[ct2][rh] += v0 + v1;
                        sQ[ct2][rh] += v0 * v0 + v1 * v1;
                    }
                }
            }
#pragma unroll
            for (int ct2 = 0; ct2 < 2; ct2++)
#pragma unroll
                for (int rh = 0; rh < 2; rh++) {
                    float s1 = sS[ct2][rh], q1 = sQ[ct2][rh];
                    s1 += __shfl_xor_sync(0xffffffffu, s1, 1);
                    s1 += __shfl_xor_sync(0xffffffffu, s1, 2);
                    q1 += __shfl_xor_sync(0xffffffffu, q1, 1);
                    q1 += __shfl_xor_sync(0xffffffffu, q1, 2);
                    if ((lane & 3) == 0) {
                        int c_loc = warp_cg * 32 + ct2 * 16 + (lane >> 2) + rh * 8;
                        redS[c_loc * 2 + warp_mg] = s1;
                        redQ[c_loc * 2 + warp_mg] = q1;
                    }
                }
            __syncthreads();
            if (tid < 128) {
                float ss = redS[tid * 2] + redS[tid * 2 + 1];
                float qq = redQ[tid * 2] + redQ[tid * 2 + 1];
                size_t po = (((size_t)b * 512 + blockIdx.x) * AH_ + ct * 128 + tid) * 2;
                part[po] = ss; part[po + 1] = qq;
            }
        }
        CP_WAIT0();
        __syncthreads();
    }
}

// ---------------- attn GEMM2 (fp16 HMMA; c-halved, pe on the fly) ------------
#define A2_A      0
#define A2_B(s)   (16384 + (s) * 16384)
#define A2_STG    49152
#define A2_PES    65536
#define A2_SIDX   99328
#define SMEM_ATT2 99840

__device__ __forceinline__ void attn2_cpasync(uint32_t sb, int s, int cq, int ch,
                                              const __half* hbase, const uint4* w2img,
                                              int tid) {
    const uint4* src = w2img + (size_t)cq * 2048 + ch * 1024;
    uint32_t bdst = sb + A2_B(s);
#pragma unroll
    for (int it = 0; it < 4; it++) {
        int i = it * 256 + tid;
        cp_async16(bdst + i * 16, src + i);
    }
#pragma unroll
    for (int it = 0; it < 4; it++) {
        int ch2 = it * 256 + tid;
        int krow = ch2 >> 4, off = ch2 & 15;
        const __half* srcr = hbase + (size_t)(cq * 64 + krow) * M_ + off * 8;
        cp_async16(sb + A2_STG + krow * 256 + off * 16, srcr);
    }
}

__device__ __forceinline__ void attn2_convert(char* smc, int cq,
                                              const float* __restrict__ scale,
                                              const float* __restrict__ shift,
                                              int wid, int lane) {
    const __half* stg = (const __half*)(smc + A2_STG);
    char* dst = smc + A2_A;
#pragma unroll
    for (int g2 = 0; g2 < 2; g2++) {
        int base_k = wid * 8 + g2 * 4;
        float X[4][4];
#pragma unroll
        for (int r = 0; r < 4; r++) {
            uint2 raw = *(const uint2*)&stg[(base_k + r) * 128 + lane * 4];
            float2 f01 = __half22float2(*(__half2*)&raw.x);
            float2 f23 = __half22float2(*(__half2*)&raw.y);
            float sc = scale[cq * 64 + base_k + r];
            float sh = shift[cq * 64 + base_k + r];
            X[0][r] = fmaxf(f01.x * sc + sh, 0.f);
            X[1][r] = fmaxf(f01.y * sc + sh, 0.f);
            X[2][r] = fmaxf(f23.x * sc + sh, 0.f);
            X[3][r] = fmaxf(f23.y * sc + sh, 0.f);
        }
#pragma unroll
        for (int mm = 0; mm < 4; mm++) {
            int m = lane * 4 + mm;
            uint32_t off = (uint32_t)((m >> 3) * 1024 + (m & 7) * 128 +
                                      ((base_k * 2) ^ ((m & 7) << 4)));
            *(uint2*)(dst + off) = make_uint2(pack_h2(X[mm][0], X[mm][1]),
                                              pack_h2(X[mm][2], X[mm][3]));
        }
    }
}

__global__ __launch_bounds__(256, 2) void attn2_hmma_kernel(
    const uint4* __restrict__ w2img, const __half* __restrict__ h,
    const float* __restrict__ scale, const float* __restrict__ shift,
    const float* __restrict__ pos, const int* __restrict__ idx,
    const float* __restrict__ wsc, const float* __restrict__ sh2,
    const uint4* __restrict__ wmid89,
    const float* __restrict__ pos_b2, const float* __restrict__ vf,
    float* __restrict__ agg) {
    extern __shared__ char smc[];
    const uint32_t sb = smem_u32(smc);
    const int tid = threadIdx.x, lane = tid & 31, wid = tid >> 5;
    const int b = blockIdx.y >> 1, ch = blockIdx.y & 1;
    const int m0 = blockIdx.x * 128;
    const int warp_m = wid >> 2, warp_c = wid & 3;

    const __half* hbase = h + (size_t)b * AH_ * M_ + m0;
    int* sidx = (int*)(smc + A2_SIDX);

    const int g = lane >> 3, lr = lane & 7;
    const int amr  = warp_m * 64 + (g & 1) * 8 + lr;
    const int bcr  = warp_c * 32 + (g >> 1) * 8 + lr;
    const int akb0 = (g >> 1) * 16;
    const int bkb0 = (g & 1) * 16;

    float acc[4][4][4];

    // ---- phase 1: compute pe tile (this c-half) into pes smem ----
    {
        if (tid < 128) sidx[tid] = idx[((size_t)b * N_ + (m0 >> 4)) * K_ + tid];
        {
            const uint4* src = wmid89 + ch * 1024;
            uint32_t dst = sb + A2_B(0);
#pragma unroll
            for (int it = 0; it < 4; it++)
                cp_async16(dst + (it * 256 + tid) * 16, src + it * 256 + tid);
            CP_COMMIT();
        }
        __syncthreads();   // sidx visible
        {
            const float* pp = pos + (size_t)b * 3 * N_;
            char* xd = smc + A2_A;
            int m = tid & 127, khalf = tid >> 7;
            int n = (m0 + m) >> 4;
            int mi = sidx[m];
            float rx = pp[n] - pp[mi];
            float ry = pp[N_ + n] - pp[N_ + mi];
            float rz = pp[2 * N_ + n] - pp[2 * N_ + mi];
#pragma unroll
            for (int k2 = 0; k2 < 16; k2++) {
                int k = khalf * 32 + k2 * 2;
                float x0 = fmaxf(wsc[3 * k] * rx + wsc[3 * k + 1] * ry + wsc[3 * k + 2] * rz + sh2[k], 0.f);
                float x1 = fmaxf(wsc[3 * k + 3] * rx + wsc[3 * k + 4] * ry + wsc[3 * k + 5] * rz + sh2[k + 1], 0.f);
                uint32_t off = (uint32_t)((m >> 3) * 1024 + (m & 7) * 128 +
                                          ((k * 2) ^ ((m & 7) << 4)));
                *(uint32_t*)(xd + off) = pack_h2(x0, x1);
            }
        }
        CP_WAIT0();
        __syncthreads();
#pragma unroll
        for (int mt = 0; mt < 4; mt++)
#pragma unroll
            for (int nt = 0; nt < 4; nt++)
#pragma unroll
                for (int j = 0; j < 4; j++) acc[mt][nt][j] = 0.0f;
        const uint32_t sA = sb + A2_A;
        const uint32_t sB = sb + A2_B(0);
#pragma unroll
        for (int ks = 0; ks < 4; ks++) {
            uint32_t Af[4][4], Bf[2][4];
#pragma unroll
            for (int mt = 0; mt < 4; mt++) {
                int m = amr + mt * 16;
                uint32_t ro = (uint32_t)((m >> 3) * 1024 + (m & 7) * 128);
                uint32_t kb = (uint32_t)((ks * 32 + akb0) ^ ((m & 7) << 4));
                ldm_x4(Af[mt], sA + ro + kb);
            }
#pragma unroll
            for (int np = 0; np < 2; np++) {
                int c = bcr + np * 16;
                uint32_t ro = (uint32_t)((c >> 3) * 1024 + (c & 7) * 128);
                uint32_t kb = (uint32_t)((ks * 32 + bkb0) ^ ((c & 7) << 4));
                ldm_x4(Bf[np], sB + ro + kb);
            }
#pragma unroll
            for (int mt = 0; mt < 4; mt++)
#pragma unroll
                for (int np = 0; np < 2; np++) {
                    mma16816h(acc[mt][np * 2],     Af[mt], &Bf[np][0]);
                    mma16816h(acc[mt][np * 2 + 1], Af[mt], &Bf[np][2]);
                }
        }
        __half* pesh = (__half*)(smc + A2_PES);
        const int r = lane >> 2;
#pragma unroll
        for (int mt = 0; mt < 4; mt++) {
            int mbase = warp_m * 64 + mt * 16;
#pragma unroll
            for (int nt = 0; nt < 4; nt++)
#pragma unroll
                for (int j = 0; j < 2; j++) {
                    int c = warp_c * 32 + nt * 8 + (lane & 3) * 2 + j;
                    float bv = pos_b2[ch * 128 + c];
                    pesh[c * 132 + mbase + r]     = __float2half(acc[mt][nt][j] + bv);
                    pesh[c * 132 + mbase + r + 8] = __float2half(acc[mt][nt][2 + j] + bv);
                }
        }
        __syncthreads();
    }

    // ---- main loop: logits GEMM (this c-half) ----
#pragma unroll
    for (int mt = 0; mt < 4; mt++)
#pragma unroll
        for (int nt = 0; nt < 4; nt++)
#pragma unroll
            for (int j = 0; j < 4; j++) acc[mt][nt][j] = 0.0f;

    attn2_cpasync(sb, 0, 0, ch, hbase, w2img, tid);
    CP_COMMIT();
    CP_WAIT0();
    __syncthreads();
    attn2_convert(smc, 0, scale, shift, wid, lane);
    __syncthreads();

    for (int cq = 0; cq < 16; cq++) {
        const int s = cq & 1;
        if (cq + 1 < 16) {
            attn2_cpasync(sb, s ^ 1, cq + 1, ch, hbase, w2img, tid);
            CP_COMMIT();
        }
        const uint32_t sA = sb + A2_A;
        const uint32_t sB = sb + A2_B(s);
#pragma unroll
        for (int ks = 0; ks < 4; ks++) {
            uint32_t Af[4][4], Bf[2][4];
#pragma unroll
            for (int mt = 0; mt < 4; mt++) {
                int m = amr + mt * 16;
                uint32_t ro = (uint32_t)((m >> 3) * 1024 + (m & 7) * 128);
                uint32_t kb = (uint32_t)((ks * 32 + akb0) ^ ((m & 7) << 4));
                ldm_x4(Af[mt], sA + ro + kb);
            }
#pragma unroll
            for (int np = 0; np < 2; np++) {
                int c = bcr + np * 16;
                uint32_t ro = (uint32_t)((c >> 3) * 1024 + (c & 7) * 128);
                uint32_t kb = (uint32_t)((ks * 32 + bkb0) ^ ((c & 7) << 4));
                ldm_x4(Bf[np], sB + ro + kb);
            }
#pragma unroll
            for (int mt = 0; mt < 4; mt++)
#pragma unroll
                for (int np = 0; np < 2; np++) {
                    mma16816h(acc[mt][np * 2],     Af[mt], &Bf[np][0]);
                    mma16816h(acc[mt][np * 2 + 1], Af[mt], &Bf[np][2]);
                }
        }
        if (cq + 1 < 16) {
            CP_WAIT0();
            __syncthreads();
            attn2_convert(smc, cq + 1, scale, shift, wid, lane);
            __syncthreads();
        }
    }
    __syncthreads();

    // ---- epilogue: softmax + aggregation ----
    const __half* pesh = (const __half*)(smc + A2_PES);
#pragma unroll
    for (int mt = 0; mt < 4; mt++) {
        const int mbase = warp_m * 64 + mt * 16;
        const int n = (m0 + mbase) >> 4;
        const int r = lane >> 2;
#pragma unroll
        for (int nt = 0; nt < 4; nt++) {
#pragma unroll
            for (int j = 0; j < 2; j++) {
                int c = warp_c * 32 + nt * 8 + (lane & 3) * 2 + j;
                float v0 = acc[mt][nt][j], v1 = acc[mt][nt][2 + j];
                float mx = fmaxf(v0, v1);
                mx = fmaxf(mx, __shfl_xor_sync(0xffffffffu, mx, 4));
                mx = fmaxf(mx, __shfl_xor_sync(0xffffffffu, mx, 8));
                mx = fmaxf(mx, __shfl_xor_sync(0xffffffffu, mx, 16));
                float e0 = __expf(v0 - mx), e1 = __expf(v1 - mx);
                float se = e0 + e1;
                se += __shfl_xor_sync(0xffffffffu, se, 4);
                se += __shfl_xor_sync(0xffffffffu, se, 8);
                se += __shfl_xor_sync(0xffffffffu, se, 16);
                float p0 = __half2float(pesh[c * 132 + mbase + r]);
                float p1 = __half2float(pesh[c * 132 + mbase + r + 8]);
                float t = e0 * p0 + e1 * p1;
                t += __shfl_xor_sync(0xffffffffu, t, 4);
                t += __shfl_xor_sync(0xffffffffu, t, 8);
                t += __shfl_xor_sync(0xffffffffu, t, 16);
                if (r == 0) {
                    size_t o = ((size_t)(b * DIM_ + ch * 128 + c)) * N_ + n;
                    agg[o] = vf[o] + t / se;
                }
            }
        }
    }
}

// ---------------- launch ----------------------------------------------------
extern "C" void kernel_launch(void* const* d_in, const int* in_sizes, int n_in,
                              void* d_out, int out_size) {
    const float* pos     = (const float*)d_in[0];
    const float* key     = (const float*)d_in[1];
    const float* query   = (const float*)d_in[2];
    const float* mlpv_w1 = (const float*)d_in[3];
    const float* mlpv_b1 = (const float*)d_in[4];
    const float* mlpv_w2 = (const float*)d_in[5];
    const float* mlpv_b2 = (const float*)d_in[6];
    const float* mlpv_ws = (const float*)d_in[7];
    const float* mlpv_bs = (const float*)d_in[8];
    const float* wk      = (const float*)d_in[9];
    const float* bk      = (const float*)d_in[10];
    const float* wq      = (const float*)d_in[11];
    const float* bq      = (const float*)d_in[12];
    const float* wv      = (const float*)d_in[13];
    const float* bv      = (const float*)d_in[14];
    const float* pos_w1  = (const float*)d_in[15];
    const float* pos_b1  = (const float*)d_in[16];
    const float* pos_g1  = (const float*)d_in[17];
    const float* pos_be1 = (const float*)d_in[18];
    const float* pos_w2  = (const float*)d_in[19];
    const float* pos_b2  = (const float*)d_in[20];
    const float* att_w1  = (const float*)d_in[21];
    const float* att_b1  = (const float*)d_in[22];
    const float* att_g1  = (const float*)d_in[23];
    const float* att_be1 = (const float*)d_in[24];
    const float* att_w2  = (const float*)d_in[25];
    const float* we      = (const float*)d_in[27];
    const float* be      = (const float*)d_in[28];
    float* out = (float*)d_out;

    void* p;
#define GETP(sym, var) cudaGetSymbolAddress(&p, sym); float* var = (float*)p;
    GETP(g_x, x_)       GETP(g_t, t_)       GETP(g_value, val)
    GETP(g_vf, vf_)     GETP(g_u, u_)
    GETP(g_agg, agg)    GETP(g_part, part)  GETP(g_partp, partp)
    GETP(g_Wuq, Wuq)    GETP(g_Wvk, Wvk)    GETP(g_bias1, bias1)
    GETP(g_wsc, wsc)    GETP(g_sh2, sh2)    GETP(g_sca, sca)
    GETP(g_sha, sha)
#undef GETP
    cudaGetSymbolAddress(&p, g_idx);      int* idx = (int*)p;
    cudaGetSymbolAddress(&p, g_vt);       __half* vt_ = (__half*)p;
    cudaGetSymbolAddress(&p, g_h);        __half* h_ = (__half*)p;
    cudaGetSymbolAddress(&p, g_w2img);    unsigned int* w2img = (unsigned int*)p;
    cudaGetSymbolAddress(&p, g_wmidimg);  unsigned int* wmidimg = (unsigned int*)p;
    cudaGetSymbolAddress(&p, g_wuqimg);   unsigned int* wuqimg = (unsigned int*)p;
    cudaGetSymbolAddress(&p, g_wvkimg);   unsigned int* wvkimg = (unsigned int*)p;

    // --- precompute folded weights + weight images ---
    smallmm_kernel<<<(AH_ * C_ + 255) / 256, 256>>>(att_w1, wq, Wuq, AH_, DIM_, C_, 0);
    smallmm_kernel<<<(AH_ * C_ + 255) / 256, 256>>>(att_w1, wk, Wvk, AH_, DIM_, C_, 0);
    bias1_kernel<<<(AH_ + 255) / 256, 256>>>(att_w1, bq, bk, pos_b2, att_b1, bias1);
    prep_w2_kernel<<<(256 * 256) / 256, 256>>>(att_w2, w2img);
    prep_wmid_kernel<<<(1280 * 16 + 255) / 256, 256>>>(att_w1, pos_w2, wmidimg);
    prep_wuv_kernel<<<(AH_ * 32 + 255) / 256, 256>>>(Wuq, wuqimg);
    prep_wuv_kernel<<<(AH_ * 32 + 255) / 256, 256>>>(Wvk, wvkimg);

    // --- front end ---
    concat_kernel<<<(unsigned)(((size_t)B_ * 2 * C_ * N_ + 255) / 256), 256>>>(key, query, x_);
    knn_kernel<<<dim3(N_ / 256, B_), 256>>>(pos, idx);
    sgemm_kernel<1><<<dim3(N_ / 128, C_ / 128, B_), 256>>>(mlpv_w1, x_, mlpv_b1, t_, nullptr, C_, 2 * C_, N_);
    sgemm_kernel<0><<<dim3(N_ / 128, C_ / 128, B_), 256>>>(mlpv_w2, t_, mlpv_b2, val, nullptr, C_, C_, N_);
    sgemm_kernel<2><<<dim3(N_ / 128, C_ / 128, B_), 256>>>(mlpv_ws, x_, mlpv_bs, val, nullptr, C_, 2 * C_, N_);
    sgemm_kernel<0><<<dim3(N_ / 128, DIM_ / 128, B_), 256>>>(wv, val, bv, vf_, nullptr, DIM_, C_, N_);

    // --- u/v on fp16 HMMA (2 blocks/SM) ---
    cudaFuncSetAttribute(uv_hmma, cudaFuncAttributeMaxDynamicSharedMemorySize, UV_SMEM);
    uv_hmma<<<dim3(N_ / 128, 4), 256, UV_SMEM>>>(query, key, wuqimg, wvkimg, u_, vt_);

    // --- pos BN via analytic moments (replaces posrel + t1) ---
    posstat_kernel<<<512, 256>>>(pos, idx, partp);
    posbn_finalize<<<1, 256>>>(partp, pos_w1, pos_b1, pos_g1, pos_be1, wsc, sh2);

    // --- fused mid on fp16 HMMA (h only, t1 on the fly, 2 blocks/SM) ---
    cudaFuncSetAttribute(fused_mid_hmma, cudaFuncAttributeMaxDynamicSharedMemorySize, FM_SMEM);
    fused_mid_hmma<<<dim3(M_ / 128, B_), 256, FM_SMEM>>>(
        pos, idx, wsc, sh2, wmidimg, bias1, u_, vt_, h_, part);
    finalize_stats<<<AH_, 256>>>(part, B_ * 512, AH_, 1, att_g1, att_be1, sca, sha, (float)((size_t)B_ * M_));

    // --- big GEMM2: c-halved fp16 HMMA, pe on the fly, 2 blocks/SM ---
    cudaFuncSetAttribute(attn2_hmma_kernel, cudaFuncAttributeMaxDynamicSharedMemorySize, SMEM_ATT2);
    attn2_hmma_kernel<<<dim3(M_ / 128, B_ * 2), 256, SMEM_ATT2>>>(
        (const uint4*)w2img, h_, sca, sha, pos, idx, wsc, sh2,
        (const uint4*)wmidimg + 8 * 1024, pos_b2, vf_, agg);

    // --- final projection + residual ---
    sgemm_kernel<4><<<dim3(N_ / 128, C_ / 128, B_), 256>>>(we, agg, be, out, val, C_, DIM_, N_);
}